// round 1
// baseline (speedup 1.0000x reference)
#include <cuda_runtime.h>

#define VIEWS 512
#define DETS  512
#define H_IMG 256
#define W_IMG 256

// Geometry constants (double-precision host math, truncated to float where used)
#define S2R_F      5.95f
#define D_IMG_F    0.006641f
// VIRDET = 0.0072 * 5.95 / (5.95 + 4.906)
#define VIRDET_D   (0.0072 * 5.95 / (5.95 + 4.906))
#define INV_VIRDET ((float)(1.0 / VIRDET_D))
#define D_ANG_F    ((float)(6.283185307179586476925286766559 / 512.0))

// Scratch for filtered projections: [2][VIEWS][DETS] (2 MB, fits L2)
__device__ float g_pf[2 * VIEWS * DETS];

// ---------------------------------------------------------------------------
// Stage 1: detector weighting + symmetric odd-tap ramp filter.
// out[d] = f0*pw[d] + sum_u fc[u] * (pw[d-(2u+1)] + pw[d+(2u+1)]),
//   fc[u] = filt[512 + 2u], f0 = filt[511].
// Even/odd compaction: for even d=2e the neighbors pw[d±(2u+1)] are the odd
// samples sOdd[e-u-1], sOdd[e+u]; for odd d=2o+1 they are sEven[o-u],
// sEven[o+u+1]. Consecutive in u -> register sliding windows fed by LDS.128.
// One block per row, 128 threads: threads 0..63 -> 4 even outputs each,
// threads 64..127 -> 4 odd outputs each.
// ---------------------------------------------------------------------------
__global__ void __launch_bounds__(128) filt_kernel(const float* __restrict__ proj,
                                                   const float* __restrict__ w,
                                                   const float* __restrict__ filt) {
    const int r = blockIdx.x;                    // 0..1023  (b*512 + v)
    const float* prow = proj + (size_t)r * DETS;

    // arr[260 + i] = sOdd_logical[i]  (i in [0,255]), zero padding elsewhere
    // arr[259 + i] = sEven_logical[i]
    __shared__ __align__(16) float sO[776];
    __shared__ __align__(16) float sE[776];
    __shared__ __align__(16) float sF[256];

    const int tid = threadIdx.x;
    for (int i = tid; i < 776; i += 128) { sO[i] = 0.0f; sE[i] = 0.0f; }
    __syncthreads();
    for (int i = tid; i < 256; i += 128) {
        sE[259 + i] = prow[2 * i]     * w[2 * i];
        sO[260 + i] = prow[2 * i + 1] * w[2 * i + 1];
        sF[i] = filt[512 + 2 * i];
    }
    __syncthreads();

    const float f0 = __ldg(&filt[511]);
    const bool evenGroup = (tid < 64);           // uniform per warp
    const int  t4 = (evenGroup ? tid : tid - 64) * 4;

    // base is 16B-aligned in both branches (260 % 4 == 0, t4 % 4 == 0)
    const float* base = evenGroup ? (sO + 260 + t4) : (sE + 260 + t4);
    const float* cent = evenGroup ? (sE + 259 + t4) : (sO + 260 + t4);

    float acc[4];
#pragma unroll
    for (int m = 0; m < 4; ++m) acc[m] = f0 * cent[m];

    // Sliding 8-wide windows. Invariant at group g (u = 4g+s):
    //   Lw[k] = base[-4-4g + k],  Rw[k] = base[4g + k]
    float Lw[8], Rw[8];
    {
        float4 a = *(const float4*)(base - 4);
        float4 b = *(const float4*)(base);
        float4 c = *(const float4*)(base + 4);
        Lw[0]=a.x; Lw[1]=a.y; Lw[2]=a.z; Lw[3]=a.w;
        Lw[4]=b.x; Lw[5]=b.y; Lw[6]=b.z; Lw[7]=b.w;
        Rw[0]=b.x; Rw[1]=b.y; Rw[2]=b.z; Rw[3]=b.w;
        Rw[4]=c.x; Rw[5]=c.y; Rw[6]=c.z; Rw[7]=c.w;
    }

    for (int g = 0; g < 64; ++g) {
        float4 fq = *(const float4*)(sF + 4 * g);      // uniform broadcast
        float fv[4] = {fq.x, fq.y, fq.z, fq.w};
#pragma unroll
        for (int s = 0; s < 4; ++s) {
#pragma unroll
            for (int m = 0; m < 4; ++m)
                acc[m] += fv[s] * (Lw[m + 3 - s] + Rw[m + s]);
        }
        // advance windows (dead loads on last iter stay inside the padded arrays)
        float4 nl = *(const float4*)(base - 8 - 4 * g);
        float4 nr = *(const float4*)(base + 8 + 4 * g);
#pragma unroll
        for (int m = 0; m < 4; ++m) { Lw[4 + m] = Lw[m]; Rw[m] = Rw[4 + m]; }
        Lw[0] = nl.x; Lw[1] = nl.y; Lw[2] = nl.z; Lw[3] = nl.w;
        Rw[4] = nr.x; Rw[5] = nr.y; Rw[6] = nr.z; Rw[7] = nr.w;
    }

    float* orow = g_pf + (size_t)r * DETS;
    if (evenGroup) {
#pragma unroll
        for (int m = 0; m < 4; ++m) orow[2 * (t4 + m)] = acc[m];
    } else {
#pragma unroll
        for (int m = 0; m < 4; ++m) orow[2 * (t4 + m) + 1] = acc[m];
    }
}

// ---------------------------------------------------------------------------
// Stage 2: per-view fan-beam backprojection.
// out[b,v,y,x] = wgt * (pf[b,v,i0]*w0 + pf[b,v,i0+1]*w1)
// Geometry is batch-independent -> compute once, serve both batches from a
// float2 shared row. 4 consecutive x per thread -> float4 stores (STG.128).
// grid = (512 views, 4 y-tiles), block = 256 threads.
// ---------------------------------------------------------------------------
__global__ void __launch_bounds__(256) bp_kernel(float* __restrict__ out) {
    const int v  = blockIdx.x;
    const int yt = blockIdx.y;

    __shared__ float2 sp[DETS];
    const int tid = threadIdx.x;
    for (int i = tid; i < DETS; i += 256) {
        sp[i] = make_float2(g_pf[(size_t)v * DETS + i],
                            g_pf[(size_t)(VIEWS + v) * DETS + i]);
    }
    float cb, sb;
    sincosf(D_ANG_F * (float)v, &sb, &cb);
    __syncthreads();

    const int lx = tid & 63;     // x-quad index (64 quads of 4 -> 256 x)
    const int ly = tid >> 6;     // 4 y rows per pass
    const int xbase = lx * 4;

    for (int yy = ly; yy < 64; yy += 4) {
        const int y = yt * 64 + yy;
        const float ysv  = (127.5f - (float)y) * D_IMG_F;
        const float yscb = ysv * cb;
        const float yssb = ysv * sb;

        float o0[4], o1[4];
#pragma unroll
        for (int m = 0; m < 4; ++m) {
            const float xv  = ((float)(xbase + m) - 127.5f) * D_IMG_F;
            const float d   = S2R_F - (xv * cb + yssb);
            const float inv = __fdividef(1.0f, d);
            const float u   = S2R_F * (yscb - xv * sb) * inv;
            float wg = S2R_F * inv; wg *= wg;
            const float t  = u * INV_VIRDET + 255.5f;
            const float tf = floorf(t);
            const int   i0 = (int)tf;
            const float frac = t - tf;
            const float w0 = (i0 >= 0  && i0 < DETS)     ? (1.0f - frac) : 0.0f;
            const float w1 = (i0 >= -1 && i0 < DETS - 1) ? frac          : 0.0f;
            const int i0c = min(max(i0, 0), DETS - 1);
            const int i1c = min(max(i0 + 1, 0), DETS - 1);
            const float2 a = sp[i0c];
            const float2 b = sp[i1c];
            o0[m] = wg * (a.x * w0 + b.x * w1);
            o1[m] = wg * (a.y * w0 + b.y * w1);
        }
        const size_t off = (((size_t)v * H_IMG) + y) * W_IMG + xbase;
        *(float4*)&out[off] = make_float4(o0[0], o0[1], o0[2], o0[3]);
        *(float4*)&out[(size_t)VIEWS * H_IMG * W_IMG + off] =
            make_float4(o1[0], o1[1], o1[2], o1[3]);
    }
}

extern "C" void kernel_launch(void* const* d_in, const int* in_sizes, int n_in,
                              void* d_out, int out_size) {
    const float* proj = (const float*)d_in[0];   // (2,1,512,512)
    const float* w    = (const float*)d_in[1];   // (512,)
    const float* filt = (const float*)d_in[2];   // (1023,)
    float* out = (float*)d_out;                  // (2,512,256,256)

    filt_kernel<<<2 * VIEWS, 128>>>(proj, w, filt);
    bp_kernel<<<dim3(VIEWS, 4), 256>>>(out);
}

// round 4
// speedup vs baseline: 1.0204x; 1.0204x over previous
#include <cuda_runtime.h>

#define VIEWS 512
#define DETS  512
#define H_IMG 256
#define W_IMG 256

#define S2R_F      5.95f
#define D_IMG_F    0.006641f
#define VIRDET_D   (0.0072 * 5.95 / (5.95 + 4.906))
#define INV_VIRDET ((float)(1.0 / VIRDET_D))
#define D_ANG_F    ((float)(6.283185307179586476925286766559 / 512.0))

// Detector index pad: i0 in [-125, 636] by geometry (|u| <= 1.5), pad by 128.
#define IPAD 128
#define SPD_N 768            // logical padded entries [0, 768)
#define SPD_SLOTS 864        // 768 + 768/8 swizzle gap headroom

// Scratch for filtered projections: [2][VIEWS][DETS]
__device__ float g_pf[2 * VIEWS * DETS];

// ---------------------------------------------------------------------------
// Stage 1: detector weighting + symmetric odd-tap ramp filter (unchanged; at
// its FMA floor ~15us per the B300 cycle model).
// ---------------------------------------------------------------------------
__global__ void __launch_bounds__(128) filt_kernel(const float* __restrict__ proj,
                                                   const float* __restrict__ w,
                                                   const float* __restrict__ filt) {
    const int r = blockIdx.x;                    // 0..1023  (b*512 + v)
    const float* prow = proj + (size_t)r * DETS;

    __shared__ __align__(16) float sO[776];
    __shared__ __align__(16) float sE[776];
    __shared__ __align__(16) float sF[256];

    const int tid = threadIdx.x;
    for (int i = tid; i < 776; i += 128) { sO[i] = 0.0f; sE[i] = 0.0f; }
    __syncthreads();
    for (int i = tid; i < 256; i += 128) {
        sE[259 + i] = prow[2 * i]     * w[2 * i];
        sO[260 + i] = prow[2 * i + 1] * w[2 * i + 1];
        sF[i] = filt[512 + 2 * i];
    }
    __syncthreads();

    const float f0 = __ldg(&filt[511]);
    const bool evenGroup = (tid < 64);
    const int  t4 = (evenGroup ? tid : tid - 64) * 4;

    const float* base = evenGroup ? (sO + 260 + t4) : (sE + 260 + t4);
    const float* cent = evenGroup ? (sE + 259 + t4) : (sO + 260 + t4);

    float acc[4];
#pragma unroll
    for (int m = 0; m < 4; ++m) acc[m] = f0 * cent[m];

    float Lw[8], Rw[8];
    {
        float4 a = *(const float4*)(base - 4);
        float4 b = *(const float4*)(base);
        float4 c = *(const float4*)(base + 4);
        Lw[0]=a.x; Lw[1]=a.y; Lw[2]=a.z; Lw[3]=a.w;
        Lw[4]=b.x; Lw[5]=b.y; Lw[6]=b.z; Lw[7]=b.w;
        Rw[0]=b.x; Rw[1]=b.y; Rw[2]=b.z; Rw[3]=b.w;
        Rw[4]=c.x; Rw[5]=c.y; Rw[6]=c.z; Rw[7]=c.w;
    }

    for (int g = 0; g < 64; ++g) {
        float4 fq = *(const float4*)(sF + 4 * g);
        float fv[4] = {fq.x, fq.y, fq.z, fq.w};
#pragma unroll
        for (int s = 0; s < 4; ++s) {
#pragma unroll
            for (int m = 0; m < 4; ++m)
                acc[m] += fv[s] * (Lw[m + 3 - s] + Rw[m + s]);
        }
        float4 nl = *(const float4*)(base - 8 - 4 * g);
        float4 nr = *(const float4*)(base + 8 + 4 * g);
#pragma unroll
        for (int m = 0; m < 4; ++m) { Lw[4 + m] = Lw[m]; Rw[m] = Rw[4 + m]; }
        Lw[0] = nl.x; Lw[1] = nl.y; Lw[2] = nl.z; Lw[3] = nl.w;
        Rw[4] = nr.x; Rw[5] = nr.y; Rw[6] = nr.z; Rw[7] = nr.w;
    }

    float* orow = g_pf + (size_t)r * DETS;
    if (evenGroup) {
#pragma unroll
        for (int m = 0; m < 4; ++m) orow[2 * (t4 + m)] = acc[m];
    } else {
#pragma unroll
        for (int m = 0; m < 4; ++m) orow[2 * (t4 + m) + 1] = acc[m];
    }
}

// ---------------------------------------------------------------------------
// Stage 2: per-view fan-beam backprojection, v2.
//  - zero-padded detector row -> no bounds checks / clamps
//  - spd[i] = (b0[i-128], b1[i-128], b0[i-127], b1[i-127]) -> one LDS.128
//    fetches the whole bilinear stencil for both batches
//  - swizzled slot = i + (i>>3) via byteoff = (18*i) & ~15 kills the
//    systematic stride-8 bank conflicts
// ---------------------------------------------------------------------------
__global__ void __launch_bounds__(256) bp_kernel(float* __restrict__ out) {
    const int v  = blockIdx.x;
    const int yt = blockIdx.y;

    __shared__ __align__(16) float4 spd[SPD_SLOTS];
    char* spd_b = (char*)spd;

    const int tid = threadIdx.x;
    const float* pf0 = g_pf + (size_t)v * DETS;
    const float* pf1 = g_pf + (size_t)(VIEWS + v) * DETS;
    for (int i = tid; i < SPD_N; i += 256) {
        const int da = i - IPAD;
        const int db = i - IPAD + 1;
        float4 e = make_float4(0.0f, 0.0f, 0.0f, 0.0f);
        if ((unsigned)da < DETS) { e.x = pf0[da]; e.y = pf1[da]; }
        if ((unsigned)db < DETS) { e.z = pf0[db]; e.w = pf1[db]; }
        *(float4*)(spd_b + ((18u * i) & ~15u)) = e;
    }
    float cb, sb;
    sincosf(D_ANG_F * (float)v, &sb, &cb);
    __syncthreads();

    const int lx = tid & 63;
    const int ly = tid >> 6;
    const int xbase = lx * 4;
    const float xv0 = ((float)xbase - 127.5f) * D_IMG_F;
    const float dd  = -D_IMG_F * cb;           // d step per x pixel
    const float dn  = -S2R_F * D_IMG_F * sb;   // num step per x pixel

    for (int yy = ly; yy < 64; yy += 4) {
        const int y = yt * 64 + yy;
        const float ysv  = (127.5f - (float)y) * D_IMG_F;
        const float yscb = ysv * cb;
        const float yssb = ysv * sb;
        const float d0 = S2R_F - yssb - xv0 * cb;
        const float n0 = S2R_F * (yscb - xv0 * sb);

        float o0[4], o1[4];
#pragma unroll
        for (int m = 0; m < 4; ++m) {
            const float d   = fmaf((float)m, dd, d0);
            const float n   = fmaf((float)m, dn, n0);
            const float inv = __fdividef(1.0f, d);
            const float g   = S2R_F * inv;
            const float wg  = g * g;
            const float t   = fmaf(n * inv, INV_VIRDET, 255.5f + (float)IPAD);
            const float tf  = truncf(t);        // t > 0 always
            const int   ip  = (int)tf;
            const float frac = t - tf;
            const float ww1 = wg * frac;
            const float ww0 = wg - ww1;         // wg*(1-frac)
            const float4 q = *(const float4*)(spd_b + ((18u * (unsigned)ip) & ~15u));
            o0[m] = fmaf(q.x, ww0, q.z * ww1);
            o1[m] = fmaf(q.y, ww0, q.w * ww1);
        }
        const size_t off = (((size_t)v * H_IMG) + y) * W_IMG + xbase;
        *(float4*)&out[off] = make_float4(o0[0], o0[1], o0[2], o0[3]);
        *(float4*)&out[(size_t)VIEWS * H_IMG * W_IMG + off] =
            make_float4(o1[0], o1[1], o1[2], o1[3]);
    }
}

extern "C" void kernel_launch(void* const* d_in, const int* in_sizes, int n_in,
                              void* d_out, int out_size) {
    const float* proj = (const float*)d_in[0];   // (2,1,512,512)
    const float* w    = (const float*)d_in[1];   // (512,)
    const float* filt = (const float*)d_in[2];   // (1023,)
    float* out = (float*)d_out;                  // (2,512,256,256)

    filt_kernel<<<2 * VIEWS, 128>>>(proj, w, filt);
    bp_kernel<<<dim3(VIEWS, 4), 256>>>(out);
}

// round 5
// speedup vs baseline: 1.1054x; 1.0834x over previous
#include <cuda_runtime.h>

#define VIEWS 512
#define DETS  512
#define H_IMG 256
#define W_IMG 256

#define S2R_F      5.95f
#define D_IMG_F    0.006641f
#define VIRDET_D   (0.0072 * 5.95 / (5.95 + 4.906))
#define INV_VIRDET ((float)(1.0 / VIRDET_D))
#define D_ANG_F    ((float)(6.283185307179586476925286766559 / 512.0))

// Detector index pad: i0 in [-125, 636] by geometry (|u| <= 1.5), pad by 128.
#define IPAD 128
#define SPD_N 768            // padded entries [0, 768)

// Scratch for filtered projections: [2][VIEWS][DETS]
__device__ float g_pf[2 * VIEWS * DETS];

// ---------------------------------------------------------------------------
// Stage 1: detector weighting + symmetric odd-tap ramp filter (at its FMA
// floor ~15us per the B300 cycle model; unchanged).
// ---------------------------------------------------------------------------
__global__ void __launch_bounds__(128) filt_kernel(const float* __restrict__ proj,
                                                   const float* __restrict__ w,
                                                   const float* __restrict__ filt) {
    const int r = blockIdx.x;                    // 0..1023  (b*512 + v)
    const float* prow = proj + (size_t)r * DETS;

    __shared__ __align__(16) float sO[776];
    __shared__ __align__(16) float sE[776];
    __shared__ __align__(16) float sF[256];

    const int tid = threadIdx.x;
    for (int i = tid; i < 776; i += 128) { sO[i] = 0.0f; sE[i] = 0.0f; }
    __syncthreads();
    for (int i = tid; i < 256; i += 128) {
        sE[259 + i] = prow[2 * i]     * w[2 * i];
        sO[260 + i] = prow[2 * i + 1] * w[2 * i + 1];
        sF[i] = filt[512 + 2 * i];
    }
    __syncthreads();

    const float f0 = __ldg(&filt[511]);
    const bool evenGroup = (tid < 64);
    const int  t4 = (evenGroup ? tid : tid - 64) * 4;

    const float* base = evenGroup ? (sO + 260 + t4) : (sE + 260 + t4);
    const float* cent = evenGroup ? (sE + 259 + t4) : (sO + 260 + t4);

    float acc[4];
#pragma unroll
    for (int m = 0; m < 4; ++m) acc[m] = f0 * cent[m];

    float Lw[8], Rw[8];
    {
        float4 a = *(const float4*)(base - 4);
        float4 b = *(const float4*)(base);
        float4 c = *(const float4*)(base + 4);
        Lw[0]=a.x; Lw[1]=a.y; Lw[2]=a.z; Lw[3]=a.w;
        Lw[4]=b.x; Lw[5]=b.y; Lw[6]=b.z; Lw[7]=b.w;
        Rw[0]=b.x; Rw[1]=b.y; Rw[2]=b.z; Rw[3]=b.w;
        Rw[4]=c.x; Rw[5]=c.y; Rw[6]=c.z; Rw[7]=c.w;
    }

    for (int g = 0; g < 64; ++g) {
        float4 fq = *(const float4*)(sF + 4 * g);
        float fv[4] = {fq.x, fq.y, fq.z, fq.w};
#pragma unroll
        for (int s = 0; s < 4; ++s) {
#pragma unroll
            for (int m = 0; m < 4; ++m)
                acc[m] += fv[s] * (Lw[m + 3 - s] + Rw[m + s]);
        }
        float4 nl = *(const float4*)(base - 8 - 4 * g);
        float4 nr = *(const float4*)(base + 8 + 4 * g);
#pragma unroll
        for (int m = 0; m < 4; ++m) { Lw[4 + m] = Lw[m]; Rw[m] = Rw[4 + m]; }
        Lw[0] = nl.x; Lw[1] = nl.y; Lw[2] = nl.z; Lw[3] = nl.w;
        Rw[4] = nr.x; Rw[5] = nr.y; Rw[6] = nr.z; Rw[7] = nr.w;
    }

    float* orow = g_pf + (size_t)r * DETS;
    if (evenGroup) {
#pragma unroll
        for (int m = 0; m < 4; ++m) orow[2 * (t4 + m)] = acc[m];
    } else {
#pragma unroll
        for (int m = 0; m < 4; ++m) orow[2 * (t4 + m) + 1] = acc[m];
    }
}

// ---------------------------------------------------------------------------
// Stage 2: per-view fan-beam backprojection, v3.
//  - adjacent lanes handle ADJACENT x pixels (thread owns x = lane + 64m),
//    so the inter-lane detector stride is <= 1.7 -> near-conflict-free LDS
//    gathers from a plain (unswizzled) float4 stencil array, with broadcast
//    dedup at views where the stride < 1.
//  - stores: 32 consecutive lanes -> 128B coalesced STG.32 lines.
// ---------------------------------------------------------------------------
__global__ void __launch_bounds__(256) bp_kernel(float* __restrict__ out) {
    const int v  = blockIdx.x;
    const int yt = blockIdx.y;

    __shared__ __align__(16) float4 spd[SPD_N];

    const int tid = threadIdx.x;
    const float* pf0 = g_pf + (size_t)v * DETS;
    const float* pf1 = g_pf + (size_t)(VIEWS + v) * DETS;
    for (int i = tid; i < SPD_N; i += 256) {
        const int da = i - IPAD;
        const int db = i - IPAD + 1;
        float4 e = make_float4(0.0f, 0.0f, 0.0f, 0.0f);
        if ((unsigned)da < DETS) { e.x = pf0[da]; e.y = pf1[da]; }
        if ((unsigned)db < DETS) { e.z = pf0[db]; e.w = pf1[db]; }
        spd[i] = e;
    }
    float cb, sb;
    sincosf(D_ANG_F * (float)v, &sb, &cb);
    __syncthreads();

    const int lane = tid & 63;   // x base; pixels at lane + 64m, m=0..3
    const int ly   = tid >> 6;
    const float xv0 = ((float)lane - 127.5f) * D_IMG_F;
    const float dd64 = -64.0f * D_IMG_F * cb;          // d step per 64 x px
    const float dn64 = -64.0f * S2R_F * D_IMG_F * sb;  // num step per 64 x px

    for (int yy = ly; yy < 64; yy += 4) {
        const int y = yt * 64 + yy;
        const float ysv  = (127.5f - (float)y) * D_IMG_F;
        const float yscb = ysv * cb;
        const float yssb = ysv * sb;
        const float d0 = S2R_F - yssb - xv0 * cb;
        const float n0 = S2R_F * (yscb - xv0 * sb);

        float o0[4], o1[4];
#pragma unroll
        for (int m = 0; m < 4; ++m) {
            const float d   = fmaf((float)m, dd64, d0);
            const float n   = fmaf((float)m, dn64, n0);
            const float inv = __fdividef(1.0f, d);
            const float g   = S2R_F * inv;
            const float wg  = g * g;
            const float t   = fmaf(n * inv, INV_VIRDET, 255.5f + (float)IPAD);
            const float tf  = truncf(t);        // t > 0 always
            const int   ip  = (int)tf;
            const float frac = t - tf;
            const float ww1 = wg * frac;
            const float ww0 = wg - ww1;         // wg*(1-frac)
            const float4 q = spd[ip];
            o0[m] = fmaf(q.x, ww0, q.z * ww1);
            o1[m] = fmaf(q.y, ww0, q.w * ww1);
        }
        float* po0 = out + (((size_t)v * H_IMG) + y) * W_IMG + lane;
        float* po1 = po0 + (size_t)VIEWS * H_IMG * W_IMG;
#pragma unroll
        for (int m = 0; m < 4; ++m) po0[64 * m] = o0[m];
#pragma unroll
        for (int m = 0; m < 4; ++m) po1[64 * m] = o1[m];
    }
}

extern "C" void kernel_launch(void* const* d_in, const int* in_sizes, int n_in,
                              void* d_out, int out_size) {
    const float* proj = (const float*)d_in[0];   // (2,1,512,512)
    const float* w    = (const float*)d_in[1];   // (512,)
    const float* filt = (const float*)d_in[2];   // (1023,)
    float* out = (float*)d_out;                  // (2,512,256,256)

    filt_kernel<<<2 * VIEWS, 128>>>(proj, w, filt);
    bp_kernel<<<dim3(VIEWS, 4), 256>>>(out);
}